// round 17
// baseline (speedup 1.0000x reference)
#include <cuda_runtime.h>
#include <cuda_bf16.h>
#include <cstdint>

// ---------------------------------------------------------------------------
// GCN 2-layer: out = A_norm( relu( A_norm(x W1) + b1 ) W2 ) + b2
// A_norm = D^-1/2 (A+I) D^-1/2.
//   - GEMM1 (50000x512x128): tf32 mma.sync (unscaled) — runs on a forked
//     stream, OVERLAPPED with the CSR build (they are data-independent)
//   - agg1 applies dinv[src] per-edge via FMA, dinv[dst] + bias + relu fused
//   - GEMM2 (50000x128x64): tf32 mma.sync with dinv rowscale epilogue
//   - 3-phase device-wide scan for CSR row offsets
// edge_index is INT32 on device (JAX x64 disabled).
// ---------------------------------------------------------------------------

#define N_NODES 50000
#define N_EDGES 1600000
#define F0 512
#define F1 128
#define F2 64

#define SCAN_T 256
#define SCAN_BLOCKS ((N_NODES + SCAN_T - 1) / SCAN_T)   // 196

// Scratch (allocation-free rules: device globals)
__device__ float g_h1  [(size_t)N_NODES * F1];   // x@W1 (unscaled)
__device__ float g_r1  [(size_t)N_NODES * F1];   // relu(agg1+b1)
__device__ float g_h2s [(size_t)N_NODES * F2];   // (r1@W2)*dinv
__device__ float g_dinv[N_NODES];
__device__ int   g_cnt [N_NODES];
__device__ int   g_row [N_NODES + 1];
__device__ int   g_cur [N_NODES];
__device__ int   g_csr [N_EDGES];
__device__ int   g_bsum[SCAN_BLOCKS];
__device__ int   g_boff[SCAN_BLOCKS];

__device__ __forceinline__ uint32_t f2tf32(float f) {
    uint32_t r;
    asm("cvt.rna.tf32.f32 %0, %1;" : "=r"(r) : "f"(f));
    return r;
}

// ---------------------------------------------------------------------------
// Degree / CSR build
// ---------------------------------------------------------------------------
__global__ void k_zero_cnt(int* cnt, int n) {
    int i = blockIdx.x * blockDim.x + threadIdx.x;
    if (i < n) cnt[i] = 0;
}
__global__ void k_count(const int* __restrict__ dst, int E, int* cnt) {
    int e = blockIdx.x * blockDim.x + threadIdx.x;
    if (e < E) atomicAdd(&cnt[dst[e]], 1);
}
__global__ void k_dinv(const int* __restrict__ cnt, float* __restrict__ dinv, int n) {
    int i = blockIdx.x * blockDim.x + threadIdx.x;
    if (i < n) dinv[i] = rsqrtf((float)(cnt[i] + 1));  // +1 self-loop
}

// ---- 3-phase device-wide exclusive scan over cnt[0..n) ----
__global__ void k_scan_bsum(const int* __restrict__ cnt, int* __restrict__ bsum, int n) {
    __shared__ int wsum[32];
    int i = blockIdx.x * SCAN_T + threadIdx.x;
    int v = (i < n) ? cnt[i] : 0;
#pragma unroll
    for (int o = 16; o > 0; o >>= 1) v += __shfl_down_sync(0xffffffffu, v, o);
    int lane = threadIdx.x & 31, wid = threadIdx.x >> 5;
    if (lane == 0) wsum[wid] = v;
    __syncthreads();
    if (wid == 0) {
        int w = (lane < SCAN_T / 32) ? wsum[lane] : 0;
#pragma unroll
        for (int o = 16; o > 0; o >>= 1) w += __shfl_down_sync(0xffffffffu, w, o);
        if (lane == 0) bsum[blockIdx.x] = w;
    }
}

__global__ void k_scan_boff(const int* __restrict__ bsum, int* __restrict__ boff,
                            int nblocks, int* __restrict__ row_n, int total) {
    __shared__ int wsum[32];
    int tid = threadIdx.x;
    int v = (tid < nblocks) ? bsum[tid] : 0;
    int lane = tid & 31, wid = tid >> 5;
    int s = v;
#pragma unroll
    for (int o = 1; o < 32; o <<= 1) {
        int t = __shfl_up_sync(0xffffffffu, s, o);
        if (lane >= o) s += t;
    }
    if (lane == 31) wsum[wid] = s;
    __syncthreads();
    if (wid == 0) {
        int w = (lane < SCAN_T / 32) ? wsum[lane] : 0;
#pragma unroll
        for (int o = 1; o < 32; o <<= 1) {
            int t = __shfl_up_sync(0xffffffffu, w, o);
            if (lane >= o) w += t;
        }
        wsum[lane] = w;
    }
    __syncthreads();
    int excl = (s - v) + (wid ? wsum[wid - 1] : 0);
    if (tid < nblocks) boff[tid] = excl;
    if (tid == 0) *row_n = total;
}

__global__ void k_scan_final(const int* __restrict__ cnt, const int* __restrict__ boff,
                             int* __restrict__ row_start, int* __restrict__ cursor, int n) {
    __shared__ int wsum[32];
    int i = blockIdx.x * SCAN_T + threadIdx.x;
    int v = (i < n) ? cnt[i] : 0;
    int lane = threadIdx.x & 31, wid = threadIdx.x >> 5;
    int s = v;
#pragma unroll
    for (int o = 1; o < 32; o <<= 1) {
        int t = __shfl_up_sync(0xffffffffu, s, o);
        if (lane >= o) s += t;
    }
    if (lane == 31) wsum[wid] = s;
    __syncthreads();
    if (wid == 0) {
        int w = (lane < SCAN_T / 32) ? wsum[lane] : 0;
#pragma unroll
        for (int o = 1; o < 32; o <<= 1) {
            int t = __shfl_up_sync(0xffffffffu, w, o);
            if (lane >= o) w += t;
        }
        wsum[lane] = w;
    }
    __syncthreads();
    int excl = (s - v) + (wid ? wsum[wid - 1] : 0) + boff[blockIdx.x];
    if (i < n) {
        row_start[i] = excl;
        cursor[i]    = excl;
    }
}

__global__ void k_fill(const int* __restrict__ src, const int* __restrict__ dst,
                       int E, int* __restrict__ cursor, int* __restrict__ csr) {
    int e = blockIdx.x * blockDim.x + threadIdx.x;
    if (e >= E) return;
    int d = dst[e];
    int pos = atomicAdd(&cursor[d], 1);
    csr[pos] = src[e];
}

// ---------------------------------------------------------------------------
// tf32 tensor-core GEMM, smem pre-converted to tf32.
//   C[M, N] = (A[M, K] @ B[K, N]) * (rowscale ? rowscale[r] : 1)
// Block tile 128xBNx32, 256 threads = 8 warps (4 rows x 2 cols).
// ---------------------------------------------------------------------------
template <int BN, int K>
__global__ void __launch_bounds__(256)
k_gemm_tf32(const float* __restrict__ A, const float* __restrict__ B,
            float* __restrict__ C, const float* __restrict__ rowscale, int M) {
    constexpr int BM = 128;
    constexpr int BK = 32;
    constexpr int NI = BN / 16;
    __shared__ uint32_t As[BM][BK + 4];
    __shared__ uint32_t Bs[BK][BN + 4];

    const int tid  = threadIdx.x;
    const int lane = tid & 31;
    const int wid  = tid >> 5;
    const int wrow = wid & 3;
    const int wcol = wid >> 2;
    const int rowBase = blockIdx.x * BM;

    float c[2][NI][4];
#pragma unroll
    for (int mi = 0; mi < 2; mi++)
#pragma unroll
        for (int ni = 0; ni < NI; ni++)
#pragma unroll
            for (int r = 0; r < 4; r++) c[mi][ni][r] = 0.0f;

    const int lq = lane >> 2;
    const int lr = lane & 3;

    for (int k0 = 0; k0 < K; k0 += BK) {
#pragma unroll
        for (int it = 0; it < 4; it++) {
            int idx = tid + it * 256;
            int r  = idx >> 3;
            int c4 = idx & 7;
            float4 v = make_float4(0.f, 0.f, 0.f, 0.f);
            int gr = rowBase + r;
            if (gr < M)
                v = *reinterpret_cast<const float4*>(&A[(size_t)gr * K + k0 + c4 * 4]);
            As[r][c4 * 4 + 0] = f2tf32(v.x);
            As[r][c4 * 4 + 1] = f2tf32(v.y);
            As[r][c4 * 4 + 2] = f2tf32(v.z);
            As[r][c4 * 4 + 3] = f2tf32(v.w);
        }
#pragma unroll
        for (int it = 0; it < (BK * BN / 4) / 256; it++) {
            int idx = tid + it * 256;
            int r  = idx / (BN / 4);
            int c4 = idx % (BN / 4);
            float4 v = *reinterpret_cast<const float4*>(&B[(size_t)(k0 + r) * BN + c4 * 4]);
            Bs[r][c4 * 4 + 0] = f2tf32(v.x);
            Bs[r][c4 * 4 + 1] = f2tf32(v.y);
            Bs[r][c4 * 4 + 2] = f2tf32(v.z);
            Bs[r][c4 * 4 + 3] = f2tf32(v.w);
        }
        __syncthreads();

#pragma unroll
        for (int kk = 0; kk < BK; kk += 8) {
            uint32_t a[2][4];
#pragma unroll
            for (int mi = 0; mi < 2; mi++) {
                int rb = wrow * 32 + mi * 16;
                a[mi][0] = As[rb + lq    ][kk + lr    ];
                a[mi][1] = As[rb + lq + 8][kk + lr    ];
                a[mi][2] = As[rb + lq    ][kk + lr + 4];
                a[mi][3] = As[rb + lq + 8][kk + lr + 4];
            }
            uint32_t b[NI][2];
#pragma unroll
            for (int ni = 0; ni < NI; ni++) {
                int cb = wcol * (BN / 2) + ni * 8;
                b[ni][0] = Bs[kk + lr    ][cb + lq];
                b[ni][1] = Bs[kk + lr + 4][cb + lq];
            }
#pragma unroll
            for (int mi = 0; mi < 2; mi++)
#pragma unroll
                for (int ni = 0; ni < NI; ni++) {
                    asm volatile(
                        "mma.sync.aligned.m16n8k8.row.col.f32.tf32.tf32.f32 "
                        "{%0,%1,%2,%3}, {%4,%5,%6,%7}, {%8,%9}, {%0,%1,%2,%3};"
                        : "+f"(c[mi][ni][0]), "+f"(c[mi][ni][1]),
                          "+f"(c[mi][ni][2]), "+f"(c[mi][ni][3])
                        : "r"(a[mi][0]), "r"(a[mi][1]), "r"(a[mi][2]), "r"(a[mi][3]),
                          "r"(b[ni][0]), "r"(b[ni][1]));
                }
        }
        __syncthreads();
    }

#pragma unroll
    for (int mi = 0; mi < 2; mi++) {
        int rb = rowBase + wrow * 32 + mi * 16;
        int r0 = rb + lq;
        int r1 = rb + lq + 8;
        float s0 = 1.0f, s1 = 1.0f;
        if (rowscale) {
            s0 = (r0 < M) ? rowscale[r0] : 0.0f;
            s1 = (r1 < M) ? rowscale[r1] : 0.0f;
        }
#pragma unroll
        for (int ni = 0; ni < NI; ni++) {
            int cb = wcol * (BN / 2) + ni * 8 + lr * 2;
            if (r0 < M) {
                float2 v0 = make_float2(c[mi][ni][0] * s0, c[mi][ni][1] * s0);
                *reinterpret_cast<float2*>(&C[(size_t)r0 * BN + cb]) = v0;
            }
            if (r1 < M) {
                float2 v1 = make_float2(c[mi][ni][2] * s1, c[mi][ni][3] * s1);
                *reinterpret_cast<float2*>(&C[(size_t)r1 * BN + cb]) = v1;
            }
        }
    }
}

// ---------------------------------------------------------------------------
// CSR gather-aggregate: one warp per node, VEC floats per lane (F = 32*VEC)
// PRESCALED=true:  hs already holds dinv[s]*h[s];    acc += hs[s]
// PRESCALED=false: hs is raw h;                       acc += h[s]*dinv[s]
//   out[n] = dinv[n] * ( edge-sum + self-term ) + bias   [relu]
// ---------------------------------------------------------------------------
template <int VEC, bool RELU, bool PRESCALED>
__global__ void k_agg_csr(const float* __restrict__ hs, const int* __restrict__ row_start,
                          const int* __restrict__ csr, const float* __restrict__ dinv,
                          const float* __restrict__ bias, float* __restrict__ out, int n) {
    constexpr int F = 32 * VEC;
    int warp = (blockIdx.x * blockDim.x + threadIdx.x) >> 5;
    int lane = threadIdx.x & 31;
    if (warp >= n) return;

    int e0 = row_start[warp];
    int e1 = row_start[warp + 1];
    float dn = dinv[warp];

    float acc[VEC];
    // self term: PRESCALED -> hs[n] (already dinv[n]*h); else h[n]*dinv[n]
    if (VEC == 4) {
        float4 v = *reinterpret_cast<const float4*>(hs + (size_t)warp * F + lane * 4);
        float sc = PRESCALED ? 1.0f : dn;
        acc[0] = v.x * sc; acc[1] = v.y * sc; acc[2] = v.z * sc; acc[3] = v.w * sc;
    } else {
        float2 v = *reinterpret_cast<const float2*>(hs + (size_t)warp * F + lane * 2);
        float sc = PRESCALED ? 1.0f : dn;
        acc[0] = v.x * sc; acc[1] = v.y * sc;
    }

    int e = e0;
    for (; e + 4 <= e1; e += 4) {
        int s0 = csr[e], s1 = csr[e + 1], s2 = csr[e + 2], s3 = csr[e + 3];
        float w0 = 1.f, w1 = 1.f, w2 = 1.f, w3 = 1.f;
        if (!PRESCALED) { w0 = dinv[s0]; w1 = dinv[s1]; w2 = dinv[s2]; w3 = dinv[s3]; }
        if (VEC == 4) {
            float4 v0 = *reinterpret_cast<const float4*>(hs + (size_t)s0 * F + lane * 4);
            float4 v1 = *reinterpret_cast<const float4*>(hs + (size_t)s1 * F + lane * 4);
            float4 v2 = *reinterpret_cast<const float4*>(hs + (size_t)s2 * F + lane * 4);
            float4 v3 = *reinterpret_cast<const float4*>(hs + (size_t)s3 * F + lane * 4);
            if (PRESCALED) {
                acc[0] += v0.x + v1.x + v2.x + v3.x;
                acc[1] += v0.y + v1.y + v2.y + v3.y;
                acc[2] += v0.z + v1.z + v2.z + v3.z;
                acc[3] += v0.w + v1.w + v2.w + v3.w;
            } else {
                acc[0] = fmaf(v0.x, w0, fmaf(v1.x, w1, fmaf(v2.x, w2, fmaf(v3.x, w3, acc[0]))));
                acc[1] = fmaf(v0.y, w0, fmaf(v1.y, w1, fmaf(v2.y, w2, fmaf(v3.y, w3, acc[1]))));
                acc[2] = fmaf(v0.z, w0, fmaf(v1.z, w1, fmaf(v2.z, w2, fmaf(v3.z, w3, acc[2]))));
                acc[3] = fmaf(v0.w, w0, fmaf(v1.w, w1, fmaf(v2.w, w2, fmaf(v3.w, w3, acc[3]))));
            }
        } else {
            float2 v0 = *reinterpret_cast<const float2*>(hs + (size_t)s0 * F + lane * 2);
            float2 v1 = *reinterpret_cast<const float2*>(hs + (size_t)s1 * F + lane * 2);
            float2 v2 = *reinterpret_cast<const float2*>(hs + (size_t)s2 * F + lane * 2);
            float2 v3 = *reinterpret_cast<const float2*>(hs + (size_t)s3 * F + lane * 2);
            if (PRESCALED) {
                acc[0] += v0.x + v1.x + v2.x + v3.x;
                acc[1] += v0.y + v1.y + v2.y + v3.y;
            } else {
                acc[0] = fmaf(v0.x, w0, fmaf(v1.x, w1, fmaf(v2.x, w2, fmaf(v3.x, w3, acc[0]))));
                acc[1] = fmaf(v0.y, w0, fmaf(v1.y, w1, fmaf(v2.y, w2, fmaf(v3.y, w3, acc[1]))));
            }
        }
    }
    for (; e < e1; e++) {
        int s = csr[e];
        float w = PRESCALED ? 1.0f : dinv[s];
        if (VEC == 4) {
            float4 v = *reinterpret_cast<const float4*>(hs + (size_t)s * F + lane * 4);
            acc[0] = fmaf(v.x, w, acc[0]); acc[1] = fmaf(v.y, w, acc[1]);
            acc[2] = fmaf(v.z, w, acc[2]); acc[3] = fmaf(v.w, w, acc[3]);
        } else {
            float2 v = *reinterpret_cast<const float2*>(hs + (size_t)s * F + lane * 2);
            acc[0] = fmaf(v.x, w, acc[0]); acc[1] = fmaf(v.y, w, acc[1]);
        }
    }

    float* op = out + (size_t)warp * F + lane * VEC;
    if (VEC == 4) {
        float4 bsv = *reinterpret_cast<const float4*>(bias + lane * 4);
        float4 r = make_float4(acc[0] * dn + bsv.x, acc[1] * dn + bsv.y,
                               acc[2] * dn + bsv.z, acc[3] * dn + bsv.w);
        if (RELU) {
            r.x = fmaxf(r.x, 0.f); r.y = fmaxf(r.y, 0.f);
            r.z = fmaxf(r.z, 0.f); r.w = fmaxf(r.w, 0.f);
        }
        *reinterpret_cast<float4*>(op) = r;
    } else {
        float2 bsv = *reinterpret_cast<const float2*>(bias + lane * 2);
        float2 r = make_float2(acc[0] * dn + bsv.x, acc[1] * dn + bsv.y);
        if (RELU) { r.x = fmaxf(r.x, 0.f); r.y = fmaxf(r.y, 0.f); }
        *reinterpret_cast<float2*>(op) = r;
    }
}

// ---------------------------------------------------------------------------
// Launcher — bind inputs BY ELEMENT COUNT; CSR build overlapped with GEMM1
// via stream fork/join (graph-capture-safe pattern).
// ---------------------------------------------------------------------------
extern "C" void kernel_launch(void* const* d_in, const int* in_sizes, int n_in,
                              void* d_out, int out_size) {
    const float* x  = nullptr;
    const int*   ei = nullptr;
    const float* W1 = nullptr;
    const float* b1 = nullptr;
    const float* W2 = nullptr;
    const float* b2 = nullptr;

    for (int i = 0; i < n_in; i++) {
        switch (in_sizes[i]) {
            case N_NODES * F0:  x  = (const float*)d_in[i]; break;
            case 2 * N_EDGES:   ei = (const int*)  d_in[i]; break;
            case F0 * F1:       W1 = (const float*)d_in[i]; break;
            case F1:            b1 = (const float*)d_in[i]; break;
            case F1 * F2:       W2 = (const float*)d_in[i]; break;
            case F2:            b2 = (const float*)d_in[i]; break;
            default: break;
        }
    }

    float* out = (float*)d_out;
    const int N = N_NODES;
    const int E = N_EDGES;
    const int* src = ei;
    const int* dst = ei + E;

    float *h1, *r1, *h2s, *dinv;
    int *cnt, *row, *cur, *csr, *bsum, *boff;
    cudaGetSymbolAddress((void**)&h1,  g_h1);
    cudaGetSymbolAddress((void**)&r1,  g_r1);
    cudaGetSymbolAddress((void**)&h2s, g_h2s);
    cudaGetSymbolAddress((void**)&dinv, g_dinv);
    cudaGetSymbolAddress((void**)&cnt, g_cnt);
    cudaGetSymbolAddress((void**)&row, g_row);
    cudaGetSymbolAddress((void**)&cur, g_cur);
    cudaGetSymbolAddress((void**)&csr, g_csr);
    cudaGetSymbolAddress((void**)&bsum, g_bsum);
    cudaGetSymbolAddress((void**)&boff, g_boff);

    const int T = 256;

    // Fork: GEMM1 (independent of graph structure) runs on a side stream,
    // concurrent with the CSR build on the main (legacy) stream.
    cudaStream_t s2;
    cudaEvent_t evFork, evJoin;
    cudaStreamCreateWithFlags(&s2, cudaStreamNonBlocking);
    cudaEventCreateWithFlags(&evFork, cudaEventDisableTiming);
    cudaEventCreateWithFlags(&evJoin, cudaEventDisableTiming);

    cudaEventRecord(evFork, 0);             // legacy stream
    cudaStreamWaitEvent(s2, evFork, 0);

    // -- side stream: GEMM1 (tf32, unscaled): h1 = x @ W1
    k_gemm_tf32<F1, F0><<<(N + 127) / 128, 256, 0, s2>>>(x, W1, h1, nullptr, N);
    cudaEventRecord(evJoin, s2);

    // -- main stream: degree histogram -> dinv, CSR offsets (3-phase) + fill
    k_zero_cnt<<<(N + T - 1) / T, T>>>(cnt, N);
    k_count<<<(E + T - 1) / T, T>>>(dst, E, cnt);
    k_dinv<<<(N + T - 1) / T, T>>>(cnt, dinv, N);
    k_scan_bsum<<<SCAN_BLOCKS, SCAN_T>>>(cnt, bsum, N);
    k_scan_boff<<<1, SCAN_T>>>(bsum, boff, SCAN_BLOCKS, &row[N], E);
    k_scan_final<<<SCAN_BLOCKS, SCAN_T>>>(cnt, boff, row, cur, N);
    k_fill<<<(E + T - 1) / T, T>>>(src, dst, E, cur, csr);

    // Join: agg1 needs both h1 (s2) and csr/dinv (main)
    cudaStreamWaitEvent(0, evJoin, 0);

    // layer-1 aggregate (per-edge dinv[src] FMA) + bias + relu -> r1
    {
        int blocks = (N * 32 + T - 1) / T;
        k_agg_csr<4, true, false><<<blocks, T>>>(h1, row, csr, dinv, b1, r1, N);
    }

    // GEMM2 (tf32): h2s = (r1 @ W2) * dinv[row]
    k_gemm_tf32<F2, F1><<<(N + 127) / 128, 256>>>(r1, W2, h2s, dinv, N);

    // layer-2 aggregate (prescaled) + bias -> out
    {
        int blocks = (N * 32 + T - 1) / T;
        k_agg_csr<2, false, true><<<blocks, T>>>(h2s, row, csr, dinv, b2, out, N);
    }
}